// round 8
// baseline (speedup 1.0000x reference)
#include <cuda_runtime.h>
#include <math.h>

#define N_NODES 20000
#define N_EDGES 320000

// ---------------- scratch (device globals) ----------------
// g_sv per node: s[0:64], v planar: 64 + 64*i + u   (i=0..2)
__device__ float g_sv[N_NODES * 256];
// g_agg per node: A[0:64], D[64:128], B planes 128+64*i+u, C planes 320+64*i+u
__device__ float g_agg[N_NODES * 512];
__device__ float g_gate[N_NODES * 64];

__device__ __forceinline__ float silu_n(float x) {
    return 1.679177f * x * (1.0f / (1.0f + __expf(-x)));
}

// ---------------- f32x2 packed-FMA helpers (Blackwell FFMA2) ----------------
typedef unsigned long long u64t;
__device__ __forceinline__ u64t pkdup(float v) {
    u64t r; asm("mov.b64 %0, {%1, %1};" : "=l"(r) : "f"(v)); return r;
}
__device__ __forceinline__ void fma2(u64t& d, u64t a, u64t b) {
    asm("fma.rn.f32x2 %0, %1, %2, %0;" : "+l"(d) : "l"(a), "l"(b));
}
__device__ __forceinline__ float2 up2(u64t v) {
    float2 r; asm("mov.b64 {%0, %1}, %2;" : "=f"(r.x), "=f"(r.y) : "l"(v)); return r;
}

// ---------------- K1: lin1, persistent blocks, weights staged in smem ----------------
__global__ void __launch_bounds__(256)
k1_lin1(const float* __restrict__ ns, const float* __restrict__ nv,
        const float* __restrict__ W1s, const float* __restrict__ W1v) {
    __shared__ float sWs[4096];
    __shared__ float sWv[4096];
    __shared__ float sIn[4][256];
    int tid = threadIdx.x;
    for (int i = tid; i < 4096; i += 256) {
        sWs[i] = W1s[i] * 0.125f;   // lin_norm folded
        sWv[i] = W1v[i] * 0.125f;
    }
    __syncthreads();
    int w = tid & 63, q = tid >> 6;
    const int ntile = N_NODES / 4;  // 5000

    for (int tile = blockIdx.x; tile < ntile; tile += gridDim.x) {
        int n0 = tile * 4;
        __syncthreads();
        for (int idx = tid; idx < 1024; idx += 256) {
            int q2 = idx >> 8, r = idx & 255;
            sIn[q2][r] = (r < 64) ? ns[(size_t)(n0 + q2) * 64 + r]
                                  : nv[(size_t)(n0 + q2) * 192 + (r - 64)];
        }
        __syncthreads();
        const float* si = sIn[q];
        float as = 0.f, a0 = 0.f, a1 = 0.f, a2 = 0.f;
#pragma unroll 4
        for (int u = 0; u < 64; u++) {
            float ws = sWs[u * 64 + w];
            float wv = sWv[u * 64 + w];
            as += si[u] * ws;
            a0 += si[64 + 3 * u + 0] * wv;
            a1 += si[64 + 3 * u + 1] * wv;
            a2 += si[64 + 3 * u + 2] * wv;
        }
        float* o = g_sv + (size_t)(n0 + q) * 256;
        o[w] = as;
        o[64 + w] = a0;
        o[128 + w] = a1;
        o[192 + w] = a2;
    }
}

// ---------------- K2: zero the aggregation buffer ----------------
__global__ void k2_zero() {
    int i = blockIdx.x * blockDim.x + threadIdx.x;
    int stride = gridDim.x * blockDim.x;
    float4* p = (float4*)g_agg;
    const int n4 = N_NODES * 512 / 4;
    for (; i < n4; i += stride) p[i] = make_float4(0.f, 0.f, 0.f, 0.f);
}

// ---------------- K3: fused edge MLP + scatter; 512 thr, 8 edges per warp-tile ----------------
// smem floats: sW0 512 + sW1dup 8192 + sW2dup(permuted) 32768 + 16 warps * 768 = 53760 -> 215040 B
#define K3_SMEM 215040
__global__ void __launch_bounds__(512, 1)
k3_edge(const float* __restrict__ esh, const float* __restrict__ emb,
        const int* __restrict__ esrc, const int* __restrict__ edst,
        const float* __restrict__ W0, const float* __restrict__ W1,
        const float* __restrict__ W2) {
    extern __shared__ float sm[];
    float* sW0  = sm;          // [8][64]           pre-scaled 1/sqrt(8)
    float* sW1d = sm + 512;    // [k=64][j dup 128] pre-scaled 0.125, {w,w} pairs
    float* sW2p = sm + 8704;   // [k=64][lane 32][j 8 dup -> 16] pre-scaled 0.125
    int tid = threadIdx.x;
    for (int i = tid; i < 512; i += 512) sW0[i] = W0[i] * 0.35355339059327373f;
    for (int i = tid; i < 4096; i += 512) {
        int k = i >> 6, j = i & 63;
        float w = W1[i] * 0.125f;              // W1[k*64+j]
        sW1d[k * 128 + 2 * j] = w;
        sW1d[k * 128 + 2 * j + 1] = w;
    }
    for (int i = tid; i < 16384; i += 512) {
        int k = i >> 8, c = i & 255;           // W2[k*256+c], c = ln + 32*j
        int ln = c & 31, j = c >> 5;
        float w = W2[i] * 0.125f;
        int d = k * 512 + ln * 16 + 2 * j;
        sW2p[d] = w;
        sW2p[d + 1] = w;
    }
    __syncthreads();

    int warp = tid >> 5, lane = tid & 31;
    float* pH  = sm + 41472 + warp * 768;  // [row 64][stride 10, edges 0..7 + pad]
    float* pEB = pH + 640;                 // 64: emb for 8 edges
    float* pSH = pEB + 64;                 // 32: sh for 8 edges
    int*   pIX = (int*)(pSH + 32);         // 16: src[8], dst[8]

    const float inv_sqrt3 = 0.57735026918962576f;
    const int ntile = N_EDGES / 8;  // 40000
    int gw = blockIdx.x * 16 + warp;
    int gstride = gridDim.x * 16;

    for (int tile = gw; tile < ntile; tile += gstride) {
        int e0 = tile * 8;
        // ---- edge meta (coalesced) ----
        if (lane < 16) pIX[lane] = (lane < 8) ? __ldg(esrc + e0 + lane)
                                              : __ldg(edst + e0 + lane - 8);
        pEB[lane]      = __ldg(emb + (size_t)e0 * 8 + lane);
        pEB[lane + 32] = __ldg(emb + (size_t)e0 * 8 + 32 + lane);
        pSH[lane]      = __ldg(esh + (size_t)e0 * 4 + lane);
        __syncwarp();

        // ---- fc0: h0[j][e] (stride 10); lane computes j = lane, lane+32 ----
#pragma unroll
        for (int e = 0; e < 8; e++) {
            float eb[8];
#pragma unroll
            for (int b = 0; b < 8; b++) eb[b] = pEB[e * 8 + b];
#pragma unroll
            for (int jj = 0; jj < 2; jj++) {
                int j = lane + 32 * jj;
                float a = 0.f;
#pragma unroll
                for (int b = 0; b < 8; b++) a += eb[b] * sW0[b * 64 + j];
                pH[j * 10 + e] = silu_n(a);
            }
        }
        __syncwarp();

        // ---- fc1: lane owns j = 2*lane, 2*lane+1; edge-paired FFMA2, all 8 edges ----
        u64t accF[2][4] = {{0ull,0ull,0ull,0ull},{0ull,0ull,0ull,0ull}};
#pragma unroll 4
        for (int k = 0; k < 64; k++) {
            ulonglong2 W = *(const ulonglong2*)(sW1d + k * 128 + 4 * lane);
#pragma unroll
            for (int ep = 0; ep < 4; ep++) {
                u64t hp = *(const u64t*)(pH + k * 10 + 2 * ep);  // {h[k][2ep], h[k][2ep+1]}
                fma2(accF[0][ep], W.x, hp);
                fma2(accF[1][ep], W.y, hp);
            }
        }
        __syncwarp();  // all reads of h0 done before overwrite
#pragma unroll
        for (int jj = 0; jj < 2; jj++) {
            int j = 2 * lane + jj;
#pragma unroll
            for (int ep = 0; ep < 4; ep++) {
                float2 v = up2(accF[jj][ep]);
                pH[j * 10 + 2 * ep]     = silu_n(v.x);
                pH[j * 10 + 2 * ep + 1] = silu_n(v.y);
            }
        }
        __syncwarp();

        // ---- fc2 in two c-half passes + split epilogue ----
        // pass p covers j = 4p..4p+3 (c = lane+32j): p0 -> A,B (needs sA), p1 -> C,D (needs v)
#pragma unroll
        for (int p = 0; p < 2; p++) {
            u64t acc[4][4];
#pragma unroll
            for (int jj = 0; jj < 4; jj++)
#pragma unroll
                for (int ep = 0; ep < 4; ep++) acc[jj][ep] = 0ull;
#pragma unroll 2
            for (int k = 0; k < 64; k++) {
                const float* wbase = sW2p + k * 512 + lane * 16 + 8 * p;
                ulonglong2 w0 = *(const ulonglong2*)(wbase);      // dup j=4p, 4p+1
                ulonglong2 w1 = *(const ulonglong2*)(wbase + 4);  // dup j=4p+2, 4p+3
#pragma unroll
                for (int ep = 0; ep < 4; ep++) {
                    u64t hp = *(const u64t*)(pH + k * 10 + 2 * ep);
                    fma2(acc[0][ep], w0.x, hp);
                    fma2(acc[1][ep], w0.y, hp);
                    fma2(acc[2][ep], w1.x, hp);
                    fma2(acc[3][ep], w1.y, hp);
                }
            }
            // epilogue for this pass
#pragma unroll
            for (int e = 0; e < 8; e++) {
                int src = pIX[e], dst = pIX[8 + e];
                src = min(max(src, 0), N_NODES - 1);
                dst = min(max(dst, 0), N_NODES - 1);
                float y0 = pSH[4 * e + 0], Y1 = pSH[4 * e + 1];
                float Y2 = pSH[4 * e + 2], Y3 = pSH[4 * e + 3];
                const float* sv = g_sv + (size_t)src * 256;
                float* ag = g_agg + (size_t)dst * 512;
#pragma unroll
                for (int half = 0; half < 2; half++) {
                    int u = lane + 32 * half;
                    float2 tlo = up2(acc[half][e >> 1]);      // j = 4p+half
                    float2 thi = up2(acc[2 + half][e >> 1]);  // j = 4p+2+half
                    float wlo = (e & 1) ? tlo.y : tlo.x;
                    float whi = (e & 1) ? thi.y : thi.x;
                    if (p == 0) {
                        // wlo = wA(u), whi = wB(u)
                        float sA = __ldg(sv + u);
                        atomicAdd(ag + u, wlo * sA * y0);
                        float bs = whi * sA;
                        atomicAdd(ag + 128 + u, bs * Y1);
                        atomicAdd(ag + 192 + u, bs * Y2);
                        atomicAdd(ag + 256 + u, bs * Y3);
                    } else {
                        // wlo = wC(u), whi = wD(u)
                        float v0 = __ldg(sv + 64 + u);
                        float v1 = __ldg(sv + 128 + u);
                        float v2 = __ldg(sv + 192 + u);
                        float cy = wlo * y0;
                        atomicAdd(ag + 320 + u, cy * v0);
                        atomicAdd(ag + 384 + u, cy * v1);
                        atomicAdd(ag + 448 + u, cy * v2);
                        atomicAdd(ag + 64 + u,
                                  whi * (v0 * Y1 + v1 * Y2 + v2 * Y3) * inv_sqrt3);
                    }
                }
            }
        }
        __syncwarp();
    }
}

// ---------------- K4a: s_h = [agg_s | ns(x)attr] @ Wcat, gates + out_s ----------------
// smem: W 49152 + ops 384*16 = 55296 floats = 221184 B; 512 threads, 16 nodes/tile
#define K4A_SMEM 221184
__global__ void __launch_bounds__(512)
k4a(const float* __restrict__ ns, const float* __restrict__ attr,
    const float* __restrict__ Wl2s, const float* __restrict__ Wscs,
    float* __restrict__ out) {
    extern __shared__ float sm[];
    float* sW = sm;            // [384][128], pre-scaled
    float* sOp = sW + 49152;   // [384][16]
    int tid = threadIdx.x;
    const float lin2n = 0.08838834764831845f;  // 1/sqrt(128)
    const float scn = 0.0625f;                 // 1/sqrt(256)
    for (int i = tid; i < 16384; i += 512) sW[i] = Wl2s[i] * lin2n;
    for (int i = tid; i < 32768; i += 512) sW[16384 + i] = Wscs[i] * scn;
    __syncthreads();

    int w = tid & 127, nh = tid >> 7;  // nh 0..3, nodes nh*4..nh*4+3
    const int ntile = N_NODES / 16;    // 1250

    for (int tile = blockIdx.x; tile < ntile; tile += gridDim.x) {
        int n0 = tile * 16;
        {
            int k = tid & 127, q = tid >> 7;
#pragma unroll
            for (int nn = 0; nn < 4; nn++) {
                int node = q * 4 + nn;
                sOp[k * 16 + node] = g_agg[(size_t)(n0 + node) * 512 + k] * 0.0625f;
            }
            for (int idx = tid; idx < 4096; idx += 512) {
                int m = idx >> 4, node = idx & 15;
                sOp[(128 + m) * 16 + node] =
                    ns[(size_t)(n0 + node) * 64 + (m >> 2)] * attr[(size_t)(n0 + node) * 4 + (m & 3)];
            }
        }
        __syncthreads();

        u64t a01 = 0ull, a23 = 0ull;
#pragma unroll 4
        for (int k = 0; k < 384; k++) {
            u64t wd = pkdup(sW[k * 128 + w]);
            ulonglong2 op = *(const ulonglong2*)(sOp + k * 16 + nh * 4);
            fma2(a01, wd, op.x);
            fma2(a23, wd, op.y);
        }
        float2 r01 = up2(a01), r23 = up2(a23);
        float r[4] = {r01.x, r01.y, r23.x, r23.y};
#pragma unroll
        for (int j = 0; j < 4; j++) {
            int n = n0 + nh * 4 + j;
            float val = silu_n(r[j]);
            if (w < 64) out[(size_t)n * 256 + w] = val;
            else        g_gate[(size_t)n * 64 + (w - 64)] = val;
        }
        __syncthreads();
    }
}

// ---------------- K4b: v_h = [agg_v | nv(x)attr] @ Wvcat, gate + out_v ----------------
// smem: W 24576 + ops 384*8*4 = 36864 floats = 147456 B; 512 threads, 8 nodes/tile
#define K4B_SMEM 147456
__global__ void __launch_bounds__(512)
k4b(const float* __restrict__ nv, const float* __restrict__ attr,
    const float* __restrict__ Wl2v, const float* __restrict__ Wscv,
    float* __restrict__ out) {
    extern __shared__ float sm[];
    float* sW = sm;            // [384][64], pre-scaled
    float* sOp = sW + 24576;   // [384][8 nodes][4]
    int tid = threadIdx.x;
    const float lin2n = 0.08838834764831845f;
    const float scn = 0.0625f;
    for (int i = tid; i < 8192; i += 512)  sW[i] = Wl2v[i] * lin2n;
    for (int i = tid; i < 16384; i += 512) sW[8192 + i] = Wscv[i] * scn;
    __syncthreads();

    int w = tid & 63, node = tid >> 6;  // node 0..7
    const int ntile = N_NODES / 8;      // 2500

    for (int tile = blockIdx.x; tile < ntile; tile += gridDim.x) {
        int n0 = tile * 8;
        for (int idx = tid; idx < 3072; idx += 512) {
            int k = idx >> 3, nd = idx & 7;
            int n = n0 + nd;
            float o0, o1, o2;
            if (k < 128) {
                const float* p = g_agg + (size_t)n * 512 + ((k < 64) ? (128 + k) : (320 + k - 64));
                o0 = p[0] * 0.0625f; o1 = p[64] * 0.0625f; o2 = p[128] * 0.0625f;
            } else {
                int m = k - 128;
                int u = m >> 2, v = m & 3;
                float av = attr[(size_t)n * 4 + v];
                const float* p = nv + (size_t)n * 192 + u * 3;
                o0 = p[0] * av; o1 = p[1] * av; o2 = p[2] * av;
            }
            *(float4*)(sOp + idx * 4) = make_float4(o0, o1, o2, 0.f);
        }
        __syncthreads();

        u64t a01 = 0ull;
        float a2 = 0.f;
#pragma unroll 4
        for (int k = 0; k < 384; k++) {
            float wk = sW[k * 64 + w];
            u64t wd = pkdup(wk);
            ulonglong2 op = *(const ulonglong2*)(sOp + (k * 8 + node) * 4);
            fma2(a01, wd, op.x);
            float2 t = up2(op.y);
            a2 += wk * t.x;
        }
        int n = n0 + node;
        float gate = g_gate[(size_t)n * 64 + w];
        float2 r = up2(a01);
        float* o = out + (size_t)n * 256 + 64 + 3 * w;
        o[0] = gate * r.x; o[1] = gate * r.y; o[2] = gate * a2;
        __syncthreads();
    }
}

// ---------------- launch ----------------
extern "C" void kernel_launch(void* const* d_in, const int* in_sizes, int n_in,
                              void* d_out, int out_size) {
    const float* node_scalars  = (const float*)d_in[0];
    const float* node_vectors  = (const float*)d_in[1];
    const float* node_attr     = (const float*)d_in[2];
    const float* edge_sh       = (const float*)d_in[3];
    const float* edge_embedded = (const float*)d_in[4];
    const int*   edge_src      = (const int*)d_in[5];
    const int*   edge_dst      = (const int*)d_in[6];
    const float* W_lin1_s      = (const float*)d_in[7];
    const float* W_lin1_v      = (const float*)d_in[8];
    const float* W_fc0         = (const float*)d_in[9];
    const float* W_fc1         = (const float*)d_in[10];
    const float* W_fc2         = (const float*)d_in[11];
    const float* W_lin2_s      = (const float*)d_in[12];
    const float* W_lin2_v      = (const float*)d_in[13];
    const float* W_sc_s        = (const float*)d_in[14];
    const float* W_sc_v        = (const float*)d_in[15];
    float* out = (float*)d_out;

    cudaFuncSetAttribute(k3_edge, cudaFuncAttributeMaxDynamicSharedMemorySize, K3_SMEM);
    cudaFuncSetAttribute(k4a, cudaFuncAttributeMaxDynamicSharedMemorySize, K4A_SMEM);
    cudaFuncSetAttribute(k4b, cudaFuncAttributeMaxDynamicSharedMemorySize, K4B_SMEM);

    k1_lin1<<<148, 256>>>(node_scalars, node_vectors, W_lin1_s, W_lin1_v);
    k2_zero<<<1024, 256>>>();
    k3_edge<<<148, 512, K3_SMEM>>>(edge_sh, edge_embedded, edge_src, edge_dst,
                                   W_fc0, W_fc1, W_fc2);
    k4a<<<148, 512, K4A_SMEM>>>(node_scalars, node_attr, W_lin2_s, W_sc_s, out);
    k4b<<<148, 512, K4B_SMEM>>>(node_vectors, node_attr, W_lin2_v, W_sc_v, out);
}

// round 9
// speedup vs baseline: 1.4633x; 1.4633x over previous
#include <cuda_runtime.h>
#include <math.h>

#define N_NODES 20000
#define N_EDGES 320000

// ---------------- scratch (device globals) ----------------
// g_sv per node: s[0:64], v planar: 64 + 64*i + u   (i=0..2)
__device__ float g_sv[N_NODES * 256];
// g_agg per node: A[0:64], D[64:128], B planes 128+64*i+u, C planes 320+64*i+u
__device__ float g_agg[N_NODES * 512];
__device__ float g_gate[N_NODES * 64];

__device__ __forceinline__ float silu_n(float x) {
    return 1.679177f * x * (1.0f / (1.0f + __expf(-x)));
}

// ---------------- f32x2 packed-FMA helpers (Blackwell FFMA2) ----------------
typedef unsigned long long u64t;
__device__ __forceinline__ u64t pkdup(float v) {
    u64t r; asm("mov.b64 %0, {%1, %1};" : "=l"(r) : "f"(v)); return r;
}
__device__ __forceinline__ void fma2(u64t& d, u64t a, u64t b) {
    asm("fma.rn.f32x2 %0, %1, %2, %0;" : "+l"(d) : "l"(a), "l"(b));
}
__device__ __forceinline__ float2 up2(u64t v) {
    float2 r; asm("mov.b64 {%0, %1}, %2;" : "=f"(r.x), "=f"(r.y) : "l"(v)); return r;
}

// ---------------- K1: lin1, persistent blocks, weights staged in smem ----------------
__global__ void __launch_bounds__(256)
k1_lin1(const float* __restrict__ ns, const float* __restrict__ nv,
        const float* __restrict__ W1s, const float* __restrict__ W1v) {
    __shared__ float sWs[4096];
    __shared__ float sWv[4096];
    __shared__ float sIn[4][256];
    int tid = threadIdx.x;
    for (int i = tid; i < 4096; i += 256) {
        sWs[i] = W1s[i] * 0.125f;   // lin_norm folded
        sWv[i] = W1v[i] * 0.125f;
    }
    __syncthreads();
    int w = tid & 63, q = tid >> 6;
    const int ntile = N_NODES / 4;  // 5000

    for (int tile = blockIdx.x; tile < ntile; tile += gridDim.x) {
        int n0 = tile * 4;
        __syncthreads();
        for (int idx = tid; idx < 1024; idx += 256) {
            int q2 = idx >> 8, r = idx & 255;
            sIn[q2][r] = (r < 64) ? ns[(size_t)(n0 + q2) * 64 + r]
                                  : nv[(size_t)(n0 + q2) * 192 + (r - 64)];
        }
        __syncthreads();
        const float* si = sIn[q];
        float as = 0.f, a0 = 0.f, a1 = 0.f, a2 = 0.f;
#pragma unroll 4
        for (int u = 0; u < 64; u++) {
            float ws = sWs[u * 64 + w];
            float wv = sWv[u * 64 + w];
            as += si[u] * ws;
            a0 += si[64 + 3 * u + 0] * wv;
            a1 += si[64 + 3 * u + 1] * wv;
            a2 += si[64 + 3 * u + 2] * wv;
        }
        float* o = g_sv + (size_t)(n0 + q) * 256;
        o[w] = as;
        o[64 + w] = a0;
        o[128 + w] = a1;
        o[192 + w] = a2;
    }
}

// ---------------- K2: zero the aggregation buffer ----------------
__global__ void k2_zero() {
    int i = blockIdx.x * blockDim.x + threadIdx.x;
    int stride = gridDim.x * blockDim.x;
    float4* p = (float4*)g_agg;
    const int n4 = N_NODES * 512 / 4;
    for (; i < n4; i += stride) p[i] = make_float4(0.f, 0.f, 0.f, 0.f);
}

// ---------------- K3: fused edge MLP + scatter; 512 thr, 8 edges per warp ----------------
// Dup-weight layouts, lane stride 2 floats (bank-conflict-free LDS.64):
//   sW1d[k][2j]        : addr k*128 + 2*j        (lane reads 2*lane and 64+2*lane)
//   sW2d[k][j][2*lane] : addr k*512 + j*64 + 2*lane
// smem floats: 512 + 8192 + 32768 + 16 warps * 752 = 53504 -> 214016 B
#define K3_SMEM 214016
__global__ void __launch_bounds__(512, 1)
k3_edge(const float* __restrict__ esh, const float* __restrict__ emb,
        const int* __restrict__ esrc, const int* __restrict__ edst,
        const float* __restrict__ W0, const float* __restrict__ W1,
        const float* __restrict__ W2) {
    extern __shared__ float sm[];
    float* sW0  = sm;          // [8][64]  pre-scaled 1/sqrt(8)
    float* sW1d = sm + 512;    // [k=64][j dup -> 128] pre-scaled 0.125
    float* sW2d = sm + 8704;   // [k=64][j=8][lane dup -> 64] pre-scaled 0.125
    int tid = threadIdx.x;
    for (int i = tid; i < 512; i += 512) sW0[i] = W0[i] * 0.35355339059327373f;
    for (int i = tid; i < 4096; i += 512) {
        int k = i >> 6, j = i & 63;
        float w = W1[i] * 0.125f;              // W1[k*64+j]
        sW1d[k * 128 + 2 * j]     = w;
        sW1d[k * 128 + 2 * j + 1] = w;
    }
    for (int i = tid; i < 16384; i += 512) {
        int k = i >> 8, c = i & 255;           // W2[k*256+c], c = ln + 32*j
        int ln = c & 31, j = c >> 5;
        float w = W2[i] * 0.125f;
        int d = k * 512 + j * 64 + 2 * ln;
        sW2d[d]     = w;
        sW2d[d + 1] = w;
    }
    __syncthreads();

    int warp = tid >> 5, lane = tid & 31;
    float* pH  = sm + 41472 + warp * 752;  // [row 64][stride 10] (8 edges + pad)
    float* pEB = pH + 640;                 // 64: emb for 8 edges
    float* pSH = pEB + 64;                 // 32: sh for 8 edges
    int*   pIX = (int*)(pSH + 32);         // 16: src[8], dst[8]

    const float inv_sqrt3 = 0.57735026918962576f;
    const int ntile = N_EDGES / 8;  // 40000
    int gw = blockIdx.x * 16 + warp;
    int gstride = gridDim.x * 16;

    for (int tile = gw; tile < ntile; tile += gstride) {
        int e0 = tile * 8;
        // ---- edge meta (coalesced) ----
        if (lane < 16) pIX[lane] = (lane < 8) ? __ldg(esrc + e0 + lane)
                                              : __ldg(edst + e0 + lane - 8);
        pEB[lane]      = __ldg(emb + (size_t)e0 * 8 + lane);
        pEB[lane + 32] = __ldg(emb + (size_t)e0 * 8 + 32 + lane);
        pSH[lane]      = __ldg(esh + (size_t)e0 * 4 + lane);
        __syncwarp();

        // ---- fc0: h0[j][e] (stride 10); lane computes j = lane, lane+32 ----
#pragma unroll
        for (int e = 0; e < 8; e++) {
            float eb[8];
#pragma unroll
            for (int b = 0; b < 8; b++) eb[b] = pEB[e * 8 + b];
#pragma unroll
            for (int jj = 0; jj < 2; jj++) {
                int j = lane + 32 * jj;
                float a = 0.f;
#pragma unroll
                for (int b = 0; b < 8; b++) a += eb[b] * sW0[b * 64 + j];
                pH[j * 10 + e] = silu_n(a);
            }
        }
        __syncwarp();

        // ---- fc1: j = lane, lane+32; edge-paired FFMA2 over all 8 edges ----
        u64t h1[2][4] = {{0ull,0ull,0ull,0ull},{0ull,0ull,0ull,0ull}};
#pragma unroll 4
        for (int k = 0; k < 64; k++) {
            u64t wd0 = *(const u64t*)(sW1d + k * 128 + 2 * lane);        // dup j=lane
            u64t wd1 = *(const u64t*)(sW1d + k * 128 + 64 + 2 * lane);   // dup j=lane+32
#pragma unroll
            for (int ep = 0; ep < 4; ep++) {
                u64t hp = *(const u64t*)(pH + k * 10 + 2 * ep);  // broadcast LDS.64
                fma2(h1[0][ep], wd0, hp);
                fma2(h1[1][ep], wd1, hp);
            }
        }
        __syncwarp();  // all h0 reads done before overwrite
#pragma unroll
        for (int kk = 0; kk < 2; kk++)
#pragma unroll
            for (int ep = 0; ep < 4; ep++) {
                float2 v = up2(h1[kk][ep]);
                pH[(lane + 32 * kk) * 10 + 2 * ep]     = silu_n(v.x);
                pH[(lane + 32 * kk) * 10 + 2 * ep + 1] = silu_n(v.y);
            }
        __syncwarp();

        // ---- fc2: lane owns c = lane + 32j (j=0..7); acc[j][edge-pair] ----
        u64t acc[8][4];
#pragma unroll
        for (int c = 0; c < 8; c++)
#pragma unroll
            for (int ep = 0; ep < 4; ep++) acc[c][ep] = 0ull;
#pragma unroll 2
        for (int k = 0; k < 64; k++) {
            u64t wd[8];
#pragma unroll
            for (int c = 0; c < 8; c++)
                wd[c] = *(const u64t*)(sW2d + k * 512 + c * 64 + 2 * lane);
#pragma unroll
            for (int ep = 0; ep < 4; ep++) {
                u64t hp = *(const u64t*)(pH + k * 10 + 2 * ep);
#pragma unroll
                for (int c = 0; c < 8; c++) fma2(acc[c][ep], wd[c], hp);
            }
        }
        __syncwarp();

        // ---- epilogue: per edge gather + coalesced atomic scatter (R5 structure) ----
#pragma unroll
        for (int e = 0; e < 8; e++) {
            int src = pIX[e], dst = pIX[8 + e];
            src = min(max(src, 0), N_NODES - 1);
            dst = min(max(dst, 0), N_NODES - 1);
            float y0 = pSH[4 * e + 0], Y1 = pSH[4 * e + 1];
            float Y2 = pSH[4 * e + 2], Y3 = pSH[4 * e + 3];
            const float* sv = g_sv + (size_t)src * 256;
            float* ag = g_agg + (size_t)dst * 512;
#pragma unroll
            for (int half = 0; half < 2; half++) {
                int u = lane + 32 * half;
                float2 tA = up2(acc[half][e >> 1]);
                float2 tB = up2(acc[half + 2][e >> 1]);
                float2 tC = up2(acc[half + 4][e >> 1]);
                float2 tD = up2(acc[half + 6][e >> 1]);
                float wA = (e & 1) ? tA.y : tA.x;
                float wB = (e & 1) ? tB.y : tB.x;
                float wC = (e & 1) ? tC.y : tC.x;
                float wD = (e & 1) ? tD.y : tD.x;
                float sA = __ldg(sv + u);
                float v0 = __ldg(sv + 64 + u);
                float v1 = __ldg(sv + 128 + u);
                float v2 = __ldg(sv + 192 + u);
                atomicAdd(ag + u, wA * sA * y0);
                atomicAdd(ag + 64 + u, wD * (v0 * Y1 + v1 * Y2 + v2 * Y3) * inv_sqrt3);
                float bs = wB * sA;
                atomicAdd(ag + 128 + u, bs * Y1);
                atomicAdd(ag + 192 + u, bs * Y2);
                atomicAdd(ag + 256 + u, bs * Y3);
                float cy = wC * y0;
                atomicAdd(ag + 320 + u, cy * v0);
                atomicAdd(ag + 384 + u, cy * v1);
                atomicAdd(ag + 448 + u, cy * v2);
            }
        }
        __syncwarp();
    }
}

// ---------------- K4a: s_h = [agg_s | ns(x)attr] @ Wcat, gates + out_s ----------------
// smem: W 49152 + ops 384*16 = 55296 floats = 221184 B; 512 threads, 16 nodes/tile
#define K4A_SMEM 221184
__global__ void __launch_bounds__(512)
k4a(const float* __restrict__ ns, const float* __restrict__ attr,
    const float* __restrict__ Wl2s, const float* __restrict__ Wscs,
    float* __restrict__ out) {
    extern __shared__ float sm[];
    float* sW = sm;            // [384][128], pre-scaled
    float* sOp = sW + 49152;   // [384][16]
    int tid = threadIdx.x;
    const float lin2n = 0.08838834764831845f;  // 1/sqrt(128)
    const float scn = 0.0625f;                 // 1/sqrt(256)
    for (int i = tid; i < 16384; i += 512) sW[i] = Wl2s[i] * lin2n;
    for (int i = tid; i < 32768; i += 512) sW[16384 + i] = Wscs[i] * scn;
    __syncthreads();

    int w = tid & 127, nh = tid >> 7;  // nh 0..3, nodes nh*4..nh*4+3
    const int ntile = N_NODES / 16;    // 1250

    for (int tile = blockIdx.x; tile < ntile; tile += gridDim.x) {
        int n0 = tile * 16;
        {
            int k = tid & 127, q = tid >> 7;
#pragma unroll
            for (int nn = 0; nn < 4; nn++) {
                int node = q * 4 + nn;
                sOp[k * 16 + node] = g_agg[(size_t)(n0 + node) * 512 + k] * 0.0625f;
            }
            for (int idx = tid; idx < 4096; idx += 512) {
                int m = idx >> 4, node = idx & 15;
                sOp[(128 + m) * 16 + node] =
                    ns[(size_t)(n0 + node) * 64 + (m >> 2)] * attr[(size_t)(n0 + node) * 4 + (m & 3)];
            }
        }
        __syncthreads();

        u64t a01 = 0ull, a23 = 0ull;
#pragma unroll 4
        for (int k = 0; k < 384; k++) {
            u64t wd = pkdup(sW[k * 128 + w]);
            ulonglong2 op = *(const ulonglong2*)(sOp + k * 16 + nh * 4);
            fma2(a01, wd, op.x);
            fma2(a23, wd, op.y);
        }
        float2 r01 = up2(a01), r23 = up2(a23);
        float r[4] = {r01.x, r01.y, r23.x, r23.y};
#pragma unroll
        for (int j = 0; j < 4; j++) {
            int n = n0 + nh * 4 + j;
            float val = silu_n(r[j]);
            if (w < 64) out[(size_t)n * 256 + w] = val;
            else        g_gate[(size_t)n * 64 + (w - 64)] = val;
        }
        __syncthreads();
    }
}

// ---------------- K4b: v_h = [agg_v | nv(x)attr] @ Wvcat, gate + out_v ----------------
// smem: W 24576 + ops 384*8*4 = 36864 floats = 147456 B; 512 threads, 8 nodes/tile
#define K4B_SMEM 147456
__global__ void __launch_bounds__(512)
k4b(const float* __restrict__ nv, const float* __restrict__ attr,
    const float* __restrict__ Wl2v, const float* __restrict__ Wscv,
    float* __restrict__ out) {
    extern __shared__ float sm[];
    float* sW = sm;            // [384][64], pre-scaled
    float* sOp = sW + 24576;   // [384][8 nodes][4]
    int tid = threadIdx.x;
    const float lin2n = 0.08838834764831845f;
    const float scn = 0.0625f;
    for (int i = tid; i < 8192; i += 512)  sW[i] = Wl2v[i] * lin2n;
    for (int i = tid; i < 16384; i += 512) sW[8192 + i] = Wscv[i] * scn;
    __syncthreads();

    int w = tid & 63, node = tid >> 6;  // node 0..7
    const int ntile = N_NODES / 8;      // 2500

    for (int tile = blockIdx.x; tile < ntile; tile += gridDim.x) {
        int n0 = tile * 8;
        for (int idx = tid; idx < 3072; idx += 512) {
            int k = idx >> 3, nd = idx & 7;
            int n = n0 + nd;
            float o0, o1, o2;
            if (k < 128) {
                const float* p = g_agg + (size_t)n * 512 + ((k < 64) ? (128 + k) : (320 + k - 64));
                o0 = p[0] * 0.0625f; o1 = p[64] * 0.0625f; o2 = p[128] * 0.0625f;
            } else {
                int m = k - 128;
                int u = m >> 2, v = m & 3;
                float av = attr[(size_t)n * 4 + v];
                const float* p = nv + (size_t)n * 192 + u * 3;
                o0 = p[0] * av; o1 = p[1] * av; o2 = p[2] * av;
            }
            *(float4*)(sOp + idx * 4) = make_float4(o0, o1, o2, 0.f);
        }
        __syncthreads();

        u64t a01 = 0ull;
        float a2 = 0.f;
#pragma unroll 4
        for (int k = 0; k < 384; k++) {
            float wk = sW[k * 64 + w];
            u64t wd = pkdup(wk);
            ulonglong2 op = *(const ulonglong2*)(sOp + (k * 8 + node) * 4);
            fma2(a01, wd, op.x);
            float2 t = up2(op.y);
            a2 += wk * t.x;
        }
        int n = n0 + node;
        float gate = g_gate[(size_t)n * 64 + w];
        float2 r = up2(a01);
        float* o = out + (size_t)n * 256 + 64 + 3 * w;
        o[0] = gate * r.x; o[1] = gate * r.y; o[2] = gate * a2;
        __syncthreads();
    }
}

// ---------------- launch ----------------
extern "C" void kernel_launch(void* const* d_in, const int* in_sizes, int n_in,
                              void* d_out, int out_size) {
    const float* node_scalars  = (const float*)d_in[0];
    const float* node_vectors  = (const float*)d_in[1];
    const float* node_attr     = (const float*)d_in[2];
    const float* edge_sh       = (const float*)d_in[3];
    const float* edge_embedded = (const float*)d_in[4];
    const int*   edge_src      = (const int*)d_in[5];
    const int*   edge_dst      = (const int*)d_in[6];
    const float* W_lin1_s      = (const float*)d_in[7];
    const float* W_lin1_v      = (const float*)d_in[8];
    const float* W_fc0         = (const float*)d_in[9];
    const float* W_fc1         = (const float*)d_in[10];
    const float* W_fc2         = (const float*)d_in[11];
    const float* W_lin2_s      = (const float*)d_in[12];
    const float* W_lin2_v      = (const float*)d_in[13];
    const float* W_sc_s        = (const float*)d_in[14];
    const float* W_sc_v        = (const float*)d_in[15];
    float* out = (float*)d_out;

    cudaFuncSetAttribute(k3_edge, cudaFuncAttributeMaxDynamicSharedMemorySize, K3_SMEM);
    cudaFuncSetAttribute(k4a, cudaFuncAttributeMaxDynamicSharedMemorySize, K4A_SMEM);
    cudaFuncSetAttribute(k4b, cudaFuncAttributeMaxDynamicSharedMemorySize, K4B_SMEM);

    k1_lin1<<<148, 256>>>(node_scalars, node_vectors, W_lin1_s, W_lin1_v);
    k2_zero<<<1024, 256>>>();
    k3_edge<<<148, 512, K3_SMEM>>>(edge_sh, edge_embedded, edge_src, edge_dst,
                                   W_fc0, W_fc1, W_fc2);
    k4a<<<148, 512, K4A_SMEM>>>(node_scalars, node_attr, W_lin2_s, W_sc_s, out);
    k4b<<<148, 512, K4B_SMEM>>>(node_vectors, node_attr, W_lin2_v, W_sc_v, out);
}

// round 11
// speedup vs baseline: 1.5655x; 1.0699x over previous
#include <cuda_runtime.h>
#include <math.h>

#define N_NODES 20000
#define N_EDGES 320000

// ---------------- scratch (device globals) ----------------
// g_sv per node: s[0:64], v planar: 64 + 64*i + u   (i=0..2)
__device__ float g_sv[N_NODES * 256];
// g_agg per node: A[0:64], D[64:128], B planes 128+64*i+u, C planes 320+64*i+u
__device__ float g_agg[N_NODES * 512];
__device__ float g_gate[N_NODES * 64];

__device__ __forceinline__ float silu_n(float x) {
    return 1.679177f * x * (1.0f / (1.0f + __expf(-x)));
}

// ---------------- f32x2 packed-FMA helpers (Blackwell FFMA2) ----------------
typedef unsigned long long u64t;
__device__ __forceinline__ u64t pkdup(float v) {
    u64t r; asm("mov.b64 %0, {%1, %1};" : "=l"(r) : "f"(v)); return r;
}
__device__ __forceinline__ void fma2(u64t& d, u64t a, u64t b) {
    asm("fma.rn.f32x2 %0, %1, %2, %0;" : "+l"(d) : "l"(a), "l"(b));
}
__device__ __forceinline__ float2 up2(u64t v) {
    float2 r; asm("mov.b64 {%0, %1}, %2;" : "=f"(r.x), "=f"(r.y) : "l"(v)); return r;
}

// ---------------- K1: lin1, persistent blocks, weights staged in smem ----------------
__global__ void __launch_bounds__(256)
k1_lin1(const float* __restrict__ ns, const float* __restrict__ nv,
        const float* __restrict__ W1s, const float* __restrict__ W1v) {
    __shared__ float sWs[4096];
    __shared__ float sWv[4096];
    __shared__ float sIn[4][256];
    int tid = threadIdx.x;
    for (int i = tid; i < 4096; i += 256) {
        sWs[i] = W1s[i] * 0.125f;   // lin_norm folded
        sWv[i] = W1v[i] * 0.125f;
    }
    __syncthreads();
    int w = tid & 63, q = tid >> 6;
    const int ntile = N_NODES / 4;  // 5000

    for (int tile = blockIdx.x; tile < ntile; tile += gridDim.x) {
        int n0 = tile * 4;
        __syncthreads();
        for (int idx = tid; idx < 1024; idx += 256) {
            int q2 = idx >> 8, r = idx & 255;
            sIn[q2][r] = (r < 64) ? ns[(size_t)(n0 + q2) * 64 + r]
                                  : nv[(size_t)(n0 + q2) * 192 + (r - 64)];
        }
        __syncthreads();
        const float* si = sIn[q];
        float as = 0.f, a0 = 0.f, a1 = 0.f, a2 = 0.f;
#pragma unroll 4
        for (int u = 0; u < 64; u++) {
            float ws = sWs[u * 64 + w];
            float wv = sWv[u * 64 + w];
            as += si[u] * ws;
            a0 += si[64 + 3 * u + 0] * wv;
            a1 += si[64 + 3 * u + 1] * wv;
            a2 += si[64 + 3 * u + 2] * wv;
        }
        float* o = g_sv + (size_t)(n0 + q) * 256;
        o[w] = as;
        o[64 + w] = a0;
        o[128 + w] = a1;
        o[192 + w] = a2;
    }
}

// ---------------- K2: zero the aggregation buffer ----------------
__global__ void k2_zero() {
    int i = blockIdx.x * blockDim.x + threadIdx.x;
    int stride = gridDim.x * blockDim.x;
    float4* p = (float4*)g_agg;
    const int n4 = N_NODES * 512 / 4;
    for (; i < n4; i += stride) p[i] = make_float4(0.f, 0.f, 0.f, 0.f);
}

// ---------------- K3: fused edge MLP + scatter; 512 thr, 8 edges per warp ----------------
// Weights: plain scalar layouts (LDS.32 stride-1, conflict-free, 1 phase) + pkdup.
// h-buffer: stride 10 -> each edge-pair operand is one aligned LDS.64 broadcast (1 phase).
// smem floats: sW0 512 + sW1 4096 + sW2 16384 + 16 warps * 752 = 33024 -> 132096 B
#define K3_SMEM 132096
__global__ void __launch_bounds__(512, 1)
k3_edge(const float* __restrict__ esh, const float* __restrict__ emb,
        const int* __restrict__ esrc, const int* __restrict__ edst,
        const float* __restrict__ W0, const float* __restrict__ W1,
        const float* __restrict__ W2) {
    extern __shared__ float sm[];
    float* sW0 = sm;           // [8][64]   pre-scaled 1/sqrt(8)
    float* sW1 = sm + 512;     // [64][64]  pre-scaled 0.125
    float* sW2 = sm + 4608;    // [64][256] pre-scaled 0.125
    int tid = threadIdx.x;
    for (int i = tid; i < 512; i += 512)   sW0[i] = W0[i] * 0.35355339059327373f;
    for (int i = tid; i < 4096; i += 512)  sW1[i] = W1[i] * 0.125f;
    for (int i = tid; i < 16384; i += 512) sW2[i] = W2[i] * 0.125f;
    __syncthreads();

    int warp = tid >> 5, lane = tid & 31;
    float* pH  = sm + 20992 + warp * 752;  // [row 64][stride 10] (8 edges + pad)
    float* pEB = pH + 640;                 // 64: emb for 8 edges
    float* pSH = pEB + 64;                 // 32: sh for 8 edges
    int*   pIX = (int*)(pSH + 32);         // 16: src[8], dst[8]

    const float inv_sqrt3 = 0.57735026918962576f;
    const int ntile = N_EDGES / 8;  // 40000
    int gw = blockIdx.x * 16 + warp;
    int gstride = gridDim.x * 16;

    for (int tile = gw; tile < ntile; tile += gstride) {
        int e0 = tile * 8;
        // ---- edge meta (coalesced) ----
        if (lane < 16) pIX[lane] = (lane < 8) ? __ldg(esrc + e0 + lane)
                                              : __ldg(edst + e0 + lane - 8);
        pEB[lane]      = __ldg(emb + (size_t)e0 * 8 + lane);
        pEB[lane + 32] = __ldg(emb + (size_t)e0 * 8 + 32 + lane);
        pSH[lane]      = __ldg(esh + (size_t)e0 * 4 + lane);
        __syncwarp();

        // ---- fc0: h0[j][e] (stride 10); lane computes j = lane, lane+32 ----
#pragma unroll
        for (int e = 0; e < 8; e++) {
            float eb[8];
#pragma unroll
            for (int b = 0; b < 8; b++) eb[b] = pEB[e * 8 + b];
#pragma unroll
            for (int jj = 0; jj < 2; jj++) {
                int j = lane + 32 * jj;
                float a = 0.f;
#pragma unroll
                for (int b = 0; b < 8; b++) a += eb[b] * sW0[b * 64 + j];
                pH[j * 10 + e] = silu_n(a);
            }
        }
        __syncwarp();

        // ---- fc1: j = lane, lane+32; edge-paired FFMA2 over all 8 edges ----
        u64t h1[2][4] = {{0ull,0ull,0ull,0ull},{0ull,0ull,0ull,0ull}};
#pragma unroll 4
        for (int k = 0; k < 64; k++) {
            u64t wd0 = pkdup(sW1[k * 64 + lane]);        // LDS.32 stride-1 + dup
            u64t wd1 = pkdup(sW1[k * 64 + lane + 32]);
#pragma unroll
            for (int ep = 0; ep < 4; ep++) {
                u64t hp = *(const u64t*)(pH + k * 10 + 2 * ep);  // LDS.64 broadcast
                fma2(h1[0][ep], wd0, hp);
                fma2(h1[1][ep], wd1, hp);
            }
        }
        __syncwarp();  // all h0 reads done before overwrite
#pragma unroll
        for (int kk = 0; kk < 2; kk++)
#pragma unroll
            for (int ep = 0; ep < 4; ep++) {
                float2 v = up2(h1[kk][ep]);
                pH[(lane + 32 * kk) * 10 + 2 * ep]     = silu_n(v.x);
                pH[(lane + 32 * kk) * 10 + 2 * ep + 1] = silu_n(v.y);
            }
        __syncwarp();

        // ---- fc2: lane owns c = lane + 32j (j=0..7); acc[j][edge-pair] ----
        u64t acc[8][4];
#pragma unroll
        for (int c = 0; c < 8; c++)
#pragma unroll
            for (int ep = 0; ep < 4; ep++) acc[c][ep] = 0ull;
#pragma unroll 2
        for (int k = 0; k < 64; k++) {
            u64t wd[8];
#pragma unroll
            for (int c = 0; c < 8; c++)
                wd[c] = pkdup(sW2[k * 256 + lane + 32 * c]);  // LDS.32 stride-1 + dup
#pragma unroll
            for (int ep = 0; ep < 4; ep++) {
                u64t hp = *(const u64t*)(pH + k * 10 + 2 * ep);  // LDS.64 broadcast
#pragma unroll
                for (int c = 0; c < 8; c++) fma2(acc[c][ep], wd[c], hp);
            }
        }
        __syncwarp();

        // ---- epilogue: per edge gather + coalesced atomic scatter ----
#pragma unroll
        for (int e = 0; e < 8; e++) {
            int src = pIX[e], dst = pIX[8 + e];
            src = min(max(src, 0), N_NODES - 1);
            dst = min(max(dst, 0), N_NODES - 1);
            float y0 = pSH[4 * e + 0], Y1 = pSH[4 * e + 1];
            float Y2 = pSH[4 * e + 2], Y3 = pSH[4 * e + 3];
            const float* sv = g_sv + (size_t)src * 256;
            float* ag = g_agg + (size_t)dst * 512;
#pragma unroll
            for (int half = 0; half < 2; half++) {
                int u = lane + 32 * half;
                float2 tA = up2(acc[half][e >> 1]);
                float2 tB = up2(acc[half + 2][e >> 1]);
                float2 tC = up2(acc[half + 4][e >> 1]);
                float2 tD = up2(acc[half + 6][e >> 1]);
                float wA = (e & 1) ? tA.y : tA.x;
                float wB = (e & 1) ? tB.y : tB.x;
                float wC = (e & 1) ? tC.y : tC.x;
                float wD = (e & 1) ? tD.y : tD.x;
                float sA = __ldg(sv + u);
                float v0 = __ldg(sv + 64 + u);
                float v1 = __ldg(sv + 128 + u);
                float v2 = __ldg(sv + 192 + u);
                atomicAdd(ag + u, wA * sA * y0);
                atomicAdd(ag + 64 + u, wD * (v0 * Y1 + v1 * Y2 + v2 * Y3) * inv_sqrt3);
                float bs = wB * sA;
                atomicAdd(ag + 128 + u, bs * Y1);
                atomicAdd(ag + 192 + u, bs * Y2);
                atomicAdd(ag + 256 + u, bs * Y3);
                float cy = wC * y0;
                atomicAdd(ag + 320 + u, cy * v0);
                atomicAdd(ag + 384 + u, cy * v1);
                atomicAdd(ag + 448 + u, cy * v2);
            }
        }
        __syncwarp();
    }
}

// ---------------- K4a: s_h = [agg_s | ns(x)attr] @ Wcat, gates + out_s ----------------
// smem: W 49152 + ops 384*16 = 55296 floats = 221184 B; 512 threads, 16 nodes/tile
#define K4A_SMEM 221184
__global__ void __launch_bounds__(512)
k4a(const float* __restrict__ ns, const float* __restrict__ attr,
    const float* __restrict__ Wl2s, const float* __restrict__ Wscs,
    float* __restrict__ out) {
    extern __shared__ float sm[];
    float* sW = sm;            // [384][128], pre-scaled
    float* sOp = sW + 49152;   // [384][16]
    int tid = threadIdx.x;
    const float lin2n = 0.08838834764831845f;  // 1/sqrt(128)
    const float scn = 0.0625f;                 // 1/sqrt(256)
    for (int i = tid; i < 16384; i += 512) sW[i] = Wl2s[i] * lin2n;
    for (int i = tid; i < 32768; i += 512) sW[16384 + i] = Wscs[i] * scn;
    __syncthreads();

    int w = tid & 127, nh = tid >> 7;  // nh 0..3, nodes nh*4..nh*4+3
    const int ntile = N_NODES / 16;    // 1250

    for (int tile = blockIdx.x; tile < ntile; tile += gridDim.x) {
        int n0 = tile * 16;
        {
            int k = tid & 127, q = tid >> 7;
#pragma unroll
            for (int nn = 0; nn < 4; nn++) {
                int node = q * 4 + nn;
                sOp[k * 16 + node] = g_agg[(size_t)(n0 + node) * 512 + k] * 0.0625f;
            }
            for (int idx = tid; idx < 4096; idx += 512) {
                int m = idx >> 4, node = idx & 15;
                sOp[(128 + m) * 16 + node] =
                    ns[(size_t)(n0 + node) * 64 + (m >> 2)] * attr[(size_t)(n0 + node) * 4 + (m & 3)];
            }
        }
        __syncthreads();

        u64t a01 = 0ull, a23 = 0ull;
#pragma unroll 4
        for (int k = 0; k < 384; k++) {
            u64t wd = pkdup(sW[k * 128 + w]);
            ulonglong2 op = *(const ulonglong2*)(sOp + k * 16 + nh * 4);
            fma2(a01, wd, op.x);
            fma2(a23, wd, op.y);
        }
        float2 r01 = up2(a01), r23 = up2(a23);
        float r[4] = {r01.x, r01.y, r23.x, r23.y};
#pragma unroll
        for (int j = 0; j < 4; j++) {
            int n = n0 + nh * 4 + j;
            float val = silu_n(r[j]);
            if (w < 64) out[(size_t)n * 256 + w] = val;
            else        g_gate[(size_t)n * 64 + (w - 64)] = val;
        }
        __syncthreads();
    }
}

// ---------------- K4b: v_h = [agg_v | nv(x)attr] @ Wvcat, gate + out_v ----------------
// smem: W 24576 + ops 384*8*4 = 36864 floats = 147456 B; 512 threads, 8 nodes/tile
#define K4B_SMEM 147456
__global__ void __launch_bounds__(512)
k4b(const float* __restrict__ nv, const float* __restrict__ attr,
    const float* __restrict__ Wl2v, const float* __restrict__ Wscv,
    float* __restrict__ out) {
    extern __shared__ float sm[];
    float* sW = sm;            // [384][64], pre-scaled
    float* sOp = sW + 24576;   // [384][8 nodes][4]
    int tid = threadIdx.x;
    const float lin2n = 0.08838834764831845f;
    const float scn = 0.0625f;
    for (int i = tid; i < 8192; i += 512)  sW[i] = Wl2v[i] * lin2n;
    for (int i = tid; i < 16384; i += 512) sW[8192 + i] = Wscv[i] * scn;
    __syncthreads();

    int w = tid & 63, node = tid >> 6;  // node 0..7
    const int ntile = N_NODES / 8;      // 2500

    for (int tile = blockIdx.x; tile < ntile; tile += gridDim.x) {
        int n0 = tile * 8;
        for (int idx = tid; idx < 3072; idx += 512) {
            int k = idx >> 3, nd = idx & 7;
            int n = n0 + nd;
            float o0, o1, o2;
            if (k < 128) {
                const float* p = g_agg + (size_t)n * 512 + ((k < 64) ? (128 + k) : (320 + k - 64));
                o0 = p[0] * 0.0625f; o1 = p[64] * 0.0625f; o2 = p[128] * 0.0625f;
            } else {
                int m = k - 128;
                int u = m >> 2, v = m & 3;
                float av = attr[(size_t)n * 4 + v];
                const float* p = nv + (size_t)n * 192 + u * 3;
                o0 = p[0] * av; o1 = p[1] * av; o2 = p[2] * av;
            }
            *(float4*)(sOp + idx * 4) = make_float4(o0, o1, o2, 0.f);
        }
        __syncthreads();

        u64t a01 = 0ull;
        float a2 = 0.f;
#pragma unroll 4
        for (int k = 0; k < 384; k++) {
            float wk = sW[k * 64 + w];
            u64t wd = pkdup(wk);
            ulonglong2 op = *(const ulonglong2*)(sOp + (k * 8 + node) * 4);
            fma2(a01, wd, op.x);
            float2 t = up2(op.y);
            a2 += wk * t.x;
        }
        int n = n0 + node;
        float gate = g_gate[(size_t)n * 64 + w];
        float2 r = up2(a01);
        float* o = out + (size_t)n * 256 + 64 + 3 * w;
        o[0] = gate * r.x; o[1] = gate * r.y; o[2] = gate * a2;
        __syncthreads();
    }
}

// ---------------- launch ----------------
extern "C" void kernel_launch(void* const* d_in, const int* in_sizes, int n_in,
                              void* d_out, int out_size) {
    const float* node_scalars  = (const float*)d_in[0];
    const float* node_vectors  = (const float*)d_in[1];
    const float* node_attr     = (const float*)d_in[2];
    const float* edge_sh       = (const float*)d_in[3];
    const float* edge_embedded = (const float*)d_in[4];
    const int*   edge_src      = (const int*)d_in[5];
    const int*   edge_dst      = (const int*)d_in[6];
    const float* W_lin1_s      = (const float*)d_in[7];
    const float* W_lin1_v      = (const float*)d_in[8];
    const float* W_fc0         = (const float*)d_in[9];
    const float* W_fc1         = (const float*)d_in[10];
    const float* W_fc2         = (const float*)d_in[11];
    const float* W_lin2_s      = (const float*)d_in[12];
    const float* W_lin2_v      = (const float*)d_in[13];
    const float* W_sc_s        = (const float*)d_in[14];
    const float* W_sc_v        = (const float*)d_in[15];
    float* out = (float*)d_out;

    cudaFuncSetAttribute(k3_edge, cudaFuncAttributeMaxDynamicSharedMemorySize, K3_SMEM);
    cudaFuncSetAttribute(k4a, cudaFuncAttributeMaxDynamicSharedMemorySize, K4A_SMEM);
    cudaFuncSetAttribute(k4b, cudaFuncAttributeMaxDynamicSharedMemorySize, K4B_SMEM);

    k1_lin1<<<148, 256>>>(node_scalars, node_vectors, W_lin1_s, W_lin1_v);
    k2_zero<<<1024, 256>>>();
    k3_edge<<<148, 512, K3_SMEM>>>(edge_sh, edge_embedded, edge_src, edge_dst,
                                   W_fc0, W_fc1, W_fc2);
    k4a<<<148, 512, K4A_SMEM>>>(node_scalars, node_attr, W_lin2_s, W_sc_s, out);
    k4b<<<148, 512, K4B_SMEM>>>(node_vectors, node_attr, W_lin2_v, W_sc_v, out);
}